// round 7
// baseline (speedup 1.0000x reference)
#include <cuda_runtime.h>

#define BB   64
#define HH   384
#define NPLT 16
#define NG   25
#define CAND 625    // NG*NG
#define LF   400    // HH + NPLT
#define NTHR 704    // 22 warps
#define NW   22
#define JW   128    // j window per pass (3 passes)
#define NGRP 4      // thread groups per pass (each does 32 j)
#define GSZ  176    // threads per group (175 active: 7 kx-tiles x 25 ky)
#define TROW 28     // padded table row (floats); 28*4B=112B, 16B-aligned rows

#define LOG2E_F  1.4426950408889634f
#define LOG2PI_F 1.8378770664093453f

__device__ __forceinline__ float ex2f(float x) {
    float r;
    asm("ex2.approx.ftz.f32 %0, %1;" : "=f"(r) : "f"(x));
    return r;
}

// ---------------------------------------------------------------------------
// Fully fused kernel: one block per batch does everything.
//  P0: grid bounds (points 0/1 of ALL batches -> minx/maxx from point 0's two
//      coords, miny/maxy from point 1's), linspace grids, constants.
//  P1: S[k] = sum_j exp(bt_j - c*dx^2 - c*dy^2) via separable tables
//      Bx[j][kx], Ay[j][ky] and a register-tiled rank-384 outer product.
//      3 passes of 128 j; within a pass, 4 groups x 32 j; each active thread
//      owns 4 kx x 1 ky (1 LDS.128 + 1 LDS + 4 FFMA per j).
//  P2: 16-step sequential argmin (packed (S_bits<<32|k) min, first-index
//      tie-break) + incremental S update with each new prediction.
//  P3: GMM loglik: logp_i = log(sum_{j<i} e_j*g_ij) - log(sum_{j<i} e_j) - C,
//      e_j = exp(beta*t_j) (the exp(-beta*t_i) factor cancels).
// ---------------------------------------------------------------------------
__global__ __launch_bounds__(NTHR, 1)
void k_fused(const float* __restrict__ curr,
             const float* __restrict__ itime,
             const float* __restrict__ hist,
             const float* __restrict__ beta_p,
             const float* __restrict__ logsig_p,
             float* __restrict__ out) {
    // tables (phases 1) and gmm arrays (phase 3) share this buffer
    __shared__ __align__(16) float tabbuf[2 * JW * TROW];  // 28672 B
    __shared__ float sxa[JW], sya[JW], sbta[JW];
    __shared__ float Spart[NGRP * CAND];                   // 10000 B
    __shared__ float xl[NG], yl[NG];
    __shared__ float bounds[4];
    __shared__ float sct[NPLT], spx[NPLT], spy[NPLT];
    __shared__ unsigned long long wmin[NW];
    __shared__ unsigned long long sbest;
    __shared__ float wacc[NW];

    const int b = blockIdx.x;
    const int t = threadIdx.x;
    const int w = t >> 5, lane = t & 31;

    float* Bx = tabbuf;             // [JW][TROW]
    float* Ay = tabbuf + JW * TROW; // [JW][TROW]

    const float beta = beta_p[0];
    const float ls   = logsig_p[0];
    const float sig  = __expf(ls);
    const float c2   = (0.5f / (sig * sig)) * LOG2E_F;

    // ---- P0: bounds. warp w in {0,1} reduces history POINT index w ----
    if (w < 2) {
        float a0 = hist[lane * (HH * 2) + 2 * w + 0];
        float a1 = hist[lane * (HH * 2) + 2 * w + 1];
        float b0 = hist[(lane + 32) * (HH * 2) + 2 * w + 0];
        float b1 = hist[(lane + 32) * (HH * 2) + 2 * w + 1];
        float mn = fminf(fminf(a0, a1), fminf(b0, b1));
        float mx = fmaxf(fmaxf(a0, a1), fmaxf(b0, b1));
#pragma unroll
        for (int o = 16; o; o >>= 1) {
            mn = fminf(mn, __shfl_xor_sync(0xffffffffu, mn, o));
            mx = fmaxf(mx, __shfl_xor_sync(0xffffffffu, mx, o));
        }
        if (lane == 0) { bounds[2 * w] = mn; bounds[2 * w + 1] = mx; }
    }
    if (t < NPLT) sct[t] = curr[b * NPLT + t];
    __syncthreads();

    if (t < NG) {
        float minx = bounds[0], maxx = bounds[1];
        float miny = bounds[2], maxy = bounds[3];
        xl[t] = (t == NG - 1) ? maxx : minx + (maxx - minx) * ((float)t / (float)(NG - 1));
        yl[t] = (t == NG - 1) ? maxy : miny + (maxy - miny) * ((float)t / (float)(NG - 1));
    }
    __syncthreads();

    // ---- P1: factorized S ----
    const int g  = t / GSZ;        // 0..3
    const int gi = t - g * GSZ;    // 0..175
    const bool gact = (gi < 175);
    const int tx = gi % 7;         // kx tile (4 wide)
    const int ky = gi / 7;         // 0..24
    float ac0 = 0.f, ac1 = 0.f, ac2 = 0.f, ac3 = 0.f;

    for (int p = 0; p < 3; p++) {
        // stage this j-window
        if (t < JW) {
            int j = p * JW + t;
            sxa[t]  = hist[b * (HH * 2) + 2 * j];
            sya[t]  = hist[b * (HH * 2) + 2 * j + 1];
            sbta[t] = beta * itime[b * HH + j] * LOG2E_F;
        }
        __syncthreads();
        // build tables (pad cols 25..27 with 0)
        for (int e = t; e < JW * TROW; e += NTHR) {
            int j = e / TROW, kc = e - j * TROW;
            if (kc < NG) {
                float dx = xl[kc] - sxa[j];
                float dy = yl[kc] - sya[j];
                Bx[e] = ex2f(fmaf(-c2, dx * dx, sbta[j]));
                Ay[e] = ex2f(-c2 * dy * dy);
            } else {
                Bx[e] = 0.f;
                Ay[e] = 0.f;
            }
        }
        __syncthreads();
        // accumulate: group g handles local j in [g*32, g*32+32)
        if (gact) {
            const int j0 = g * 32;
#pragma unroll 4
            for (int jl = j0; jl < j0 + 32; jl++) {
                float4 bx = *(const float4*)&Bx[jl * TROW + tx * 4];
                float  ay = Ay[jl * TROW + ky];
                ac0 = fmaf(bx.x, ay, ac0);
                ac1 = fmaf(bx.y, ay, ac1);
                ac2 = fmaf(bx.z, ay, ac2);
                ac3 = fmaf(bx.w, ay, ac3);
            }
        }
        __syncthreads();  // before next pass overwrites tables
    }
    // write partials (only kx < 25)
    if (gact) {
        int kx = tx * 4;
        float* dst = &Spart[g * CAND + ky * NG + kx];
        dst[0] = ac0;
        if (kx + 1 < NG) dst[1] = ac1;
        if (kx + 2 < NG) dst[2] = ac2;
        if (kx + 3 < NG) dst[3] = ac3;
    }
    __syncthreads();

    // ---- P2: 16-step argmin loop. thread t owns candidate k=t (t<625) ----
    const bool act = (t < CAND);
    float s = 0.f, cx = 0.f, cy = 0.f;
    if (act) {
        s = Spart[t] + Spart[CAND + t] + Spart[2 * CAND + t] + Spart[3 * CAND + t];
        cx = xl[t % NG];
        cy = yl[t / NG];
    }

    for (int i = 0; i < NPLT; i++) {
        unsigned long long key = act
            ? ((((unsigned long long)__float_as_uint(s)) << 32) | (unsigned)t)
            : 0xFFFFFFFFFFFFFFFFULL;
#pragma unroll
        for (int o = 16; o; o >>= 1) {
            unsigned long long other = __shfl_xor_sync(0xffffffffu, key, o);
            key = (other < key) ? other : key;
        }
        if (lane == 0) wmin[w] = key;
        __syncthreads();
        if (w == 0) {
            unsigned long long kk = (lane < NW) ? wmin[lane] : 0xFFFFFFFFFFFFFFFFULL;
#pragma unroll
            for (int o = 16; o; o >>= 1) {
                unsigned long long other = __shfl_xor_sync(0xffffffffu, kk, o);
                kk = (other < kk) ? other : kk;
            }
            if (lane == 0) sbest = kk;
        }
        __syncthreads();

        unsigned idx = (unsigned)(sbest & 0xffffffffu);
        float px = xl[idx % NG];
        float py = yl[idx / NG];
        if (t == 0) {
            out[BB + (i * BB + b) * 2 + 0] = px;
            out[BB + (i * BB + b) * 2 + 1] = py;
            spx[i] = px; spy[i] = py;
        }
        if (act && i < NPLT - 1) {
            float dx = cx - px;
            float dy = cy - py;
            float bt = beta * sct[i] * LOG2E_F;
            s += ex2f(fmaf(-c2, fmaf(dx, dx, dy * dy), bt));
        }
        __syncthreads();  // wmin/sbest reuse + spx visibility
    }

    // ---- P3: GMM loglik (tabbuf reused for px/py/exj) ----
    float* px = tabbuf;
    float* py = tabbuf + LF;
    float* ex = tabbuf + 2 * LF;
    for (int j = t; j < HH; j += NTHR) {
        px[j] = hist[b * (HH * 2) + 2 * j];
        py[j] = hist[b * (HH * 2) + 2 * j + 1];
        ex[j] = ex2f(beta * itime[b * HH + j] * LOG2E_F);
    }
    if (t < NPLT) {
        px[HH + t] = spx[t];
        py[HH + t] = spy[t];
        ex[HH + t] = ex2f(beta * sct[t] * LOG2E_F);
    }
    __syncthreads();

    float acc = 0.f;
    for (int i = 1 + w; i < LF; i += NW) {
        float xi = px[i], yi = py[i];
        float s1 = 0.f, s2 = 0.f;
        for (int j = lane; j < i; j += 32) {
            float e = ex[j];
            float dx = xi - px[j];
            float dy = yi - py[j];
            s1 += e;
            s2 = fmaf(e, ex2f(-c2 * fmaf(dx, dx, dy * dy)), s2);
        }
#pragma unroll
        for (int o = 16; o; o >>= 1) {
            s1 += __shfl_down_sync(0xffffffffu, s1, o);
            s2 += __shfl_down_sync(0xffffffffu, s2, o);
        }
        if (lane == 0) acc += __logf(s2) - __logf(s1);
    }
    if (lane == 0) wacc[w] = acc;
    __syncthreads();

    if (t == 0) {
        float tot = 0.f;
#pragma unroll
        for (int q = 0; q < NW; q++) tot += wacc[q];
        float C = 2.f * ls + LOG2PI_F;
        float x0 = px[0], y0 = py[0];
        out[b] = -0.5f * (x0 * x0 + y0 * y0) - LOG2PI_F + tot - (float)(LF - 1) * C;
    }
}

// ---------------------------------------------------------------------------
extern "C" void kernel_launch(void* const* d_in, const int* in_sizes, int n_in,
                              void* d_out, int out_size) {
    const float* curr   = (const float*)d_in[0];  // (64,16)
    const float* itime  = (const float*)d_in[1];  // (64,384)
    const float* hist   = (const float*)d_in[2];  // (64,384,2)
    // d_in[3..5] (expected_data, aux_*) are dead inputs
    const float* beta   = (const float*)d_in[6];
    const float* logsig = (const float*)d_in[7];
    float* out = (float*)d_out;  // [64 loglik][16*64*2 predicted]

    k_fused<<<BB, NTHR>>>(curr, itime, hist, beta, logsig, out);
}

// round 9
// speedup vs baseline: 1.3148x; 1.3148x over previous
#include <cuda_runtime.h>

#define BB   64
#define HH   384
#define NPLT 16
#define NG   25
#define CAND 625   // NG*NG
#define LF   400   // HH + NPLT
#define JS   4     // j-chunks in k_base
#define JCH  96    // j per chunk (4*96 = 384)
#define TROW 28    // padded table row (floats): 7 tiles x 4, 112B rows

#define LOG2E_F  1.4426950408889634f
#define LOG2PI_F 1.8378770664093453f

// persistent scratch (allocation-free rule: __device__ globals)
__device__ float g_xlim[NG];
__device__ float g_ylim[NG];
__device__ float g_Spart[JS][BB * CAND];
__device__ float g_pred[BB * NPLT * 2];
__device__ float g_c2;    // (0.5/sigma^2) * LOG2E
__device__ float g_beta;

__device__ __forceinline__ float ex2f(float x) {
    float r;
    asm("ex2.approx.ftz.f32 %0, %1;" : "=f"(r) : "f"(x));
    return r;
}
__device__ __forceinline__ unsigned redux_min_u32(unsigned v) {
    unsigned d;
    asm("redux.sync.min.u32 %0, %1, 0xffffffff;" : "=r"(d) : "r"(v));
    return d;
}

// ---------------------------------------------------------------------------
// Kernel 1: factorized base-S partials.
//   S[b][k] = sum_j Bx[j][kx] * Ay[j][ky],
//   Bx = exp(beta*t_j*log2e - c2*dx^2), Ay = exp(-c2*dy^2).
// grid (4 j-chunks, 64 batches), 192 threads. 175 active compute threads own
// a 4(kx) x 1(ky) register tile: per j 1 LDS.128 + 1 LDS + 4 FFMA.
// Every block recomputes grid bounds (cheap, removes any cross-block dep):
//   minx/maxx = min/max over BOTH coords of history POINT 0 (all batches)
//   miny/maxy = min/max over BOTH coords of history POINT 1 (all batches)
// ---------------------------------------------------------------------------
__global__ __launch_bounds__(192, 2)
void k_base(const float* __restrict__ itime,
            const float* __restrict__ hist,
            const float* __restrict__ beta_p,
            const float* __restrict__ logsig_p) {
    __shared__ __align__(16) float Bx[JCH * TROW];  // 10752 B
    __shared__ __align__(16) float Ay[JCH * TROW];  // 10752 B
    __shared__ float sxa[JCH], sya[JCH], sbta[JCH];
    __shared__ float xl[NG], yl[NG];
    __shared__ float bounds[4];

    const int jc = blockIdx.x;   // 0..3
    const int b  = blockIdx.y;
    const int t  = threadIdx.x;  // 192
    const int w  = t >> 5, lane = t & 31;

    // ---- bounds: warp w in {0,1} reduces history POINT index w ----
    if (w < 2) {
        float a0 = hist[lane * (HH * 2) + 2 * w + 0];
        float a1 = hist[lane * (HH * 2) + 2 * w + 1];
        float b0 = hist[(lane + 32) * (HH * 2) + 2 * w + 0];
        float b1 = hist[(lane + 32) * (HH * 2) + 2 * w + 1];
        float mn = fminf(fminf(a0, a1), fminf(b0, b1));
        float mx = fmaxf(fmaxf(a0, a1), fmaxf(b0, b1));
#pragma unroll
        for (int o = 16; o; o >>= 1) {
            mn = fminf(mn, __shfl_xor_sync(0xffffffffu, mn, o));
            mx = fmaxf(mx, __shfl_xor_sync(0xffffffffu, mx, o));
        }
        if (lane == 0) { bounds[2 * w] = mn; bounds[2 * w + 1] = mx; }
    }

    const float beta = beta_p[0];
    const float sig  = __expf(logsig_p[0]);
    const float c2   = (0.5f / (sig * sig)) * LOG2E_F;

    // stage this j-chunk
    for (int j = t; j < JCH; j += 192) {
        int jj = jc * JCH + j;
        sxa[j]  = hist[b * (HH * 2) + 2 * jj];
        sya[j]  = hist[b * (HH * 2) + 2 * jj + 1];
        sbta[j] = beta * itime[b * HH + jj] * LOG2E_F;
    }
    __syncthreads();

    if (t < NG) {
        float minx = bounds[0], maxx = bounds[1];
        float miny = bounds[2], maxy = bounds[3];
        float fx = (t == NG - 1) ? maxx : minx + (maxx - minx) * ((float)t / (float)(NG - 1));
        float fy = (t == NG - 1) ? maxy : miny + (maxy - miny) * ((float)t / (float)(NG - 1));
        xl[t] = fx; yl[t] = fy;
        if (jc == 0 && b == 0) { g_xlim[t] = fx; g_ylim[t] = fy; }
    }
    if (t == 0 && jc == 0 && b == 0) { g_c2 = c2; g_beta = beta; }
    __syncthreads();

    // build tables (pad cols 25..27 with 0)
    for (int e = t; e < JCH * TROW; e += 192) {
        int j = e / TROW, kc = e - j * TROW;
        if (kc < NG) {
            float dx = xl[kc] - sxa[j];
            float dy = yl[kc] - sya[j];
            Bx[e] = ex2f(fmaf(-c2, dx * dx, sbta[j]));
            Ay[e] = ex2f(-c2 * dy * dy);
        } else {
            Bx[e] = 0.f;
            Ay[e] = 0.f;
        }
    }
    __syncthreads();

    // register-tiled outer-product accumulation
    if (t < 175) {
        const int tx = t % 7;   // kx tile (4 wide)
        const int ky = t / 7;   // 0..24
        float ac0 = 0.f, ac1 = 0.f, ac2 = 0.f, ac3 = 0.f;
#pragma unroll 4
        for (int j = 0; j < JCH; j++) {
            float4 bx = *(const float4*)&Bx[j * TROW + tx * 4];
            float  ay = Ay[j * TROW + ky];
            ac0 = fmaf(bx.x, ay, ac0);
            ac1 = fmaf(bx.y, ay, ac1);
            ac2 = fmaf(bx.z, ay, ac2);
            ac3 = fmaf(bx.w, ay, ac3);
        }
        int kx = tx * 4;
        float* dst = &g_Spart[jc][b * CAND + ky * NG + kx];
        dst[0] = ac0;
        if (kx + 1 < NG) dst[1] = ac1;
        if (kx + 2 < NG) dst[2] = ac2;
        if (kx + 3 < NG) dst[3] = ac3;
    }
}

// ---------------------------------------------------------------------------
// Kernel 2: 16-step sequential argmin loop. 256 threads (8 warps) per batch,
// 3 candidates per thread (k = t + 256*r). Two-phase argmin per step using
// redux.sync.min.u32 (float bits of S >= 0 are order-preserving):
//   phase 1: global min value bits; phase 2: min index among equals
// -> exact first-index tie-break (matches jnp.argmin). Parity-double-buffered
// smem combine arrays -> 2 __syncthreads per step.
// Also initializes out[b] with logp0 + constant terms for k_gmm's atomics.
// ---------------------------------------------------------------------------
__global__ __launch_bounds__(256, 1)
void k_iter(const float* __restrict__ curr,
            const float* __restrict__ hist,
            const float* __restrict__ logsig_p,
            float* __restrict__ out) {
    __shared__ unsigned wval[2][8];
    __shared__ unsigned widx[2][8];
    const int b = blockIdx.x;
    const int t = threadIdx.x;  // 256
    const int w = t >> 5, lane = t & 31;
    const float c2 = g_c2, beta = g_beta;

    if (t == 0) {
        float x0 = hist[b * (HH * 2)];
        float y0 = hist[b * (HH * 2) + 1];
        float ls = logsig_p[0];
        float C = 2.f * ls + LOG2PI_F;
        out[b] = -0.5f * (x0 * x0 + y0 * y0) - LOG2PI_F - (float)(LF - 1) * C;
    }

    const int NR = 3;  // ceil(625/256)
    float s[NR], cx[NR], cy[NR];
#pragma unroll
    for (int r = 0; r < NR; r++) {
        int k = t + 256 * r;
        if (k < CAND) {
            cx[r] = g_xlim[k % NG];
            cy[r] = g_ylim[k / NG];
            s[r]  = g_Spart[0][b * CAND + k] + g_Spart[1][b * CAND + k]
                  + g_Spart[2][b * CAND + k] + g_Spart[3][b * CAND + k];
        } else {
            s[r] = __uint_as_float(0xFFFFFFFFu);  // sentinel (max bits)
            cx[r] = 0.f; cy[r] = 0.f;
        }
    }

    for (int i = 0; i < NPLT; i++) {
        const int p = i & 1;
        // phase 1: min value bits
        unsigned vb = 0xFFFFFFFFu;
#pragma unroll
        for (int r = 0; r < NR; r++) {
            unsigned u = __float_as_uint(s[r]);
            vb = (u < vb) ? u : vb;
        }
        unsigned wv = redux_min_u32(vb);
        if (lane == 0) wval[p][w] = wv;
        __syncthreads();
        unsigned gmin = wval[p][0];
#pragma unroll
        for (int q = 1; q < 8; q++) gmin = (wval[p][q] < gmin) ? wval[p][q] : gmin;

        // phase 2: min index among s == gmin
        unsigned ki = 0xFFFFFFFFu;
#pragma unroll
        for (int r = NR - 1; r >= 0; r--) {
            if (__float_as_uint(s[r]) == gmin) ki = (unsigned)(t + 256 * r);
        }
        unsigned wi = redux_min_u32(ki);
        if (lane == 0) widx[p][w] = wi;
        __syncthreads();
        unsigned idx = widx[p][0];
#pragma unroll
        for (int q = 1; q < 8; q++) idx = (widx[p][q] < idx) ? widx[p][q] : idx;

        float px = g_xlim[idx % NG];
        float py = g_ylim[idx / NG];
        if (t == 0) {
            out[BB + (i * BB + b) * 2 + 0] = px;
            out[BB + (i * BB + b) * 2 + 1] = py;
            g_pred[(b * NPLT + i) * 2 + 0] = px;
            g_pred[(b * NPLT + i) * 2 + 1] = py;
        }
        if (i < NPLT - 1) {
            float bt = beta * __ldg(&curr[b * NPLT + i]) * LOG2E_F;
#pragma unroll
            for (int r = 0; r < NR; r++) {
                int k = t + 256 * r;
                if (k < CAND) {
                    float dx = cx[r] - px;
                    float dy = cy[r] - py;
                    s[r] += ex2f(fmaf(-c2, fmaf(dx, dx, dy * dy), bt));
                }
            }
        }
    }
}

// ---------------------------------------------------------------------------
// Kernel 3: final GMM log-likelihood.
//   logp_i = log(sum_{j<i} e_j * g_ij) - log(sum_{j<i} e_j) - C
// with e_j = exp(beta*t_j) (exp(-beta*t_i) cancels), g_ij = exp(-c*sq).
// Grid (16 chunks, 64 batches), 128 thr, warp-per-row stride 64;
// one atomicAdd per block into out[b] (pre-initialized by k_iter).
// ---------------------------------------------------------------------------
__global__ void k_gmm(const float* __restrict__ itime,
                      const float* __restrict__ hist,
                      const float* __restrict__ curr,
                      float* __restrict__ out) {
    __shared__ float exj[LF], px[LF], py[LF];
    __shared__ float wacc[4];
    const int b = blockIdx.y;
    const int c = blockIdx.x;   // 16 chunks
    const int t = threadIdx.x;  // 128
    const float beta = g_beta, c2 = g_c2;

    for (int j = t; j < HH; j += 128) {
        px[j]  = hist[b * (HH * 2) + 2 * j];
        py[j]  = hist[b * (HH * 2) + 2 * j + 1];
        exj[j] = ex2f(beta * itime[b * HH + j] * LOG2E_F);
    }
    if (t < NPLT) {
        px[HH + t]  = g_pred[(b * NPLT + t) * 2 + 0];
        py[HH + t]  = g_pred[(b * NPLT + t) * 2 + 1];
        exj[HH + t] = ex2f(beta * curr[b * NPLT + t] * LOG2E_F);
    }
    __syncthreads();

    const int w = t >> 5, lane = t & 31;
    float acc = 0.f;

    for (int i = 1 + c * 4 + w; i < LF; i += 64) {
        float xi = px[i], yi = py[i];
        float s1 = 0.f, s2 = 0.f;
        for (int j = lane; j < i; j += 32) {
            float e = exj[j];
            float dx = xi - px[j];
            float dy = yi - py[j];
            float sq = fmaf(dx, dx, dy * dy);
            s1 += e;
            s2 = fmaf(e, ex2f(-c2 * sq), s2);
        }
#pragma unroll
        for (int o = 16; o; o >>= 1) {
            s1 += __shfl_down_sync(0xffffffffu, s1, o);
            s2 += __shfl_down_sync(0xffffffffu, s2, o);
        }
        if (lane == 0) acc += __logf(s2) - __logf(s1);
    }
    if (lane == 0) wacc[w] = acc;
    __syncthreads();
    if (t == 0) {
        float tot = (wacc[0] + wacc[1]) + (wacc[2] + wacc[3]);
        atomicAdd(&out[b], tot);
    }
}

// ---------------------------------------------------------------------------
extern "C" void kernel_launch(void* const* d_in, const int* in_sizes, int n_in,
                              void* d_out, int out_size) {
    const float* curr   = (const float*)d_in[0];  // (64,16)
    const float* itime  = (const float*)d_in[1];  // (64,384)
    const float* hist   = (const float*)d_in[2];  // (64,384,2)
    // d_in[3..5] (expected_data, aux_*) are dead inputs
    const float* beta   = (const float*)d_in[6];
    const float* logsig = (const float*)d_in[7];
    float* out = (float*)d_out;  // [64 loglik][16*64*2 predicted]

    k_base<<<dim3(JS, BB), 192>>>(itime, hist, beta, logsig);
    k_iter<<<BB, 256>>>(curr, hist, logsig, out);
    k_gmm<<<dim3(16, BB), 128>>>(itime, hist, curr, out);
}